// round 5
// baseline (speedup 1.0000x reference)
#include <cuda_runtime.h>
#include <math.h>

// ------------------------ problem constants ------------------------
#define Bc      2
#define NEGc    16
#define Nc      10000
#define Ec      80000
#define Dc      128
#define Lc      3
#define Kc      1000
#define BNc     20000
#define NUMRELc 237
#define EPSc    1e-5f
#define DMAXc   6016     // max dirty nodes: 4 boundary + 3*2000
#define UMAXc   2048     // max updated nodes per layer (<= B*K = 2000)

#define SCORE_BLKS 752           // DMAXc/8
#define FILL_BLKS  157           // ceil(BNc/128)

// ------------------------ device scratch (static, no runtime alloc) ------------------------
// NOTE: all state is restored to zero by k_cleanup/k_reset at the end of every
// call, so no bulk init kernel is needed (globals are zero at module load).
__device__ float g_hidden[BNc * Dc];
__device__ float g_Q[BNc * Dc];
__device__ float g_score[BNc];
__device__ int   g_dirty[BNc];
__device__ unsigned char g_sel[BNc];     // 0=not sel, 1=sel, 2=sel+valid Q
__device__ int   g_indeg[Nc];
__device__ int   g_outdeg[Nc];
__device__ int   g_inoff[Nc + 1];
__device__ int   g_cursor[Nc];
__device__ int   g_insrc[Ec];
__device__ int   g_Dlist[DMAXc];
__device__ int   g_Dcnt;
__device__ int   g_Ulist[UMAXc];
__device__ int   g_Qlist[UMAXc];
__device__ int   g_UcntA[Lc];
__device__ int   g_QcntA[Lc];
__device__ unsigned long long g_sumlogA[Lc];
__device__ float g_rel[Bc * Dc];
__device__ float g_rellin[Bc * Dc];
__device__ float g_szero;
__device__ int   g_tidx[Bc * NEGc];

// ------------------------ helpers ------------------------
__device__ __forceinline__ unsigned map_sc(float f) {
    unsigned u = __float_as_uint(f);
    if (u == 0x80000000u) u = 0u;                      // normalize -0 -> +0
    return (u & 0x80000000u) ? ~u : (u | 0x80000000u); // monotone order-preserving map
}

// ------------------------ CSR build ------------------------
__global__ void k_deg(const int* __restrict__ ei) {
    int i = blockIdx.x * 256 + threadIdx.x;
    if (i < Ec) {
        atomicAdd(&g_outdeg[ei[i]], 1);
        atomicAdd(&g_indeg[ei[Ec + i]], 1);
    }
}

__global__ void k_scan() {   // exclusive scan of indeg -> inoff (single block, 1024 thr)
    __shared__ int tot[1024];
    int t = threadIdx.x;
    const int CH = 10;
    int loc[CH];
    int s = 0;
#pragma unroll
    for (int j = 0; j < CH; j++) {
        int idx = t * CH + j;
        int v = (idx < Nc) ? g_indeg[idx] : 0;
        loc[j] = s; s += v;
    }
    tot[t] = s;
    __syncthreads();
    for (int off = 1; off < 1024; off <<= 1) {
        int v = (t >= off) ? tot[t - off] : 0;
        __syncthreads();
        tot[t] += v;
        __syncthreads();
    }
    int ex = tot[t] - s;
#pragma unroll
    for (int j = 0; j < CH; j++) {
        int idx = t * CH + j;
        if (idx < Nc) { g_inoff[idx] = ex + loc[j]; g_cursor[idx] = 0; }
    }
    if (t == 1023) g_inoff[Nc] = tot[1023];
}

__global__ void k_fill(const int* __restrict__ ei) {
    int i = blockIdx.x * 256 + threadIdx.x;
    if (i < Ec) {
        int d = ei[Ec + i];
        int pos = atomicAdd(&g_cursor[d], 1);
        g_insrc[g_inoff[d] + pos] = ei[i];
    }
}

// ------------------------ prep: indices, boundary, rel_lin, s_zero, s_init ------------------------
__global__ void k_prep(const int* __restrict__ hI, const int* __restrict__ rI,
                       const int* __restrict__ tI, const float* __restrict__ HS,
                       const float* __restrict__ RE, const float* __restrict__ linW,
                       const float* __restrict__ linb, const float* __restrict__ m1W,
                       const float* __restrict__ m1b, const float* __restrict__ m2W,
                       const float* __restrict__ m2b) {
    int k = threadIdx.x;
    __shared__ int hh[Bc], tt[Bc], rr[Bc], isT[Bc];
    __shared__ float xs[Dc];
    __shared__ float red[Dc];
    __shared__ float hvs[Dc];

    if (k < Bc) {
        int b = k;
        int t_neg = 1;
        int h0 = hI[b * NEGc];
        for (int j = 1; j < NEGc; j++) if (hI[b * NEGc + j] != h0) t_neg = 0;
        isT[b] = t_neg;
        hh[b] = t_neg ? h0 : tI[b * NEGc];
        tt[b] = t_neg ? tI[b * NEGc] : h0;
        rr[b] = t_neg ? rI[b * NEGc] : (rI[b * NEGc] + NUMRELc);
    }
    __syncthreads();

    for (int idx = k; idx < Bc * NEGc; idx += Dc) {
        int b = idx / NEGc;
        int tv = isT[b] ? tI[idx] : hI[idx];
        g_tidx[idx] = tv + b * Nc;
    }
    for (int b = 0; b < Bc; b++) g_rel[b * Dc + k] = RE[rr[b] * Dc + k];

    // reference quirk: h_vals/t_vals both use ROW 0's indices for every batch
    float hv = HS[hh[0] * Dc + k];
    float tv = HS[tt[0] * Dc + k];
    __syncthreads();

    for (int b = 0; b < Bc; b++) g_hidden[(tt[b] + b * Nc) * Dc + k] = tv;
    __syncthreads();
    for (int b = 0; b < Bc; b++) g_hidden[(hh[b] + b * Nc) * Dc + k] = hv;

    if (k == 0) {
        for (int b = 0; b < Bc; b++) {
            int nodes2[2] = { tt[b] + b * Nc, hh[b] + b * Nc };
            for (int q = 0; q < 2; q++) {
                int v = nodes2[q];
                if (atomicExch(&g_dirty[v], 1) == 0) {
                    int p = atomicAdd(&g_Dcnt, 1);
                    g_Dlist[p] = v;
                }
            }
        }
    }

    // rel_lin[b] = rel[b] @ linW[D:2D] + lin_b
    for (int b = 0; b < Bc; b++) {
        float a = linb[k];
        for (int j = 0; j < Dc; j++) a += g_rel[b * Dc + j] * linW[(Dc + j) * Dc + k];
        g_rellin[b * Dc + k] = a;
    }

    // s_zero = relu(m1_b) @ m2_W + m2_b
    red[k] = fmaxf(m1b[k], 0.f) * m2W[k];
    __syncthreads();
    for (int s = 64; s > 0; s >>= 1) {
        if (k < s) red[k] += red[k + s];
        __syncthreads();
    }
    if (k == 0) g_szero = red[0] + m2b[0];
    __syncthreads();

    // s_init[b] = _score(h_vals, rel[b]) at flat_h
    hvs[k] = hv;
    __syncthreads();
    for (int b = 0; b < Bc; b++) {
        float a = g_rellin[b * Dc + k];
        for (int j = 0; j < Dc; j++) a += hvs[j] * linW[j * Dc + k];
        float x = a * hv;
        xs[k] = x;
        __syncthreads();
        float h2 = m1b[k];
        for (int j = 0; j < Dc; j++) h2 += xs[j] * m1W[j * Dc + k];
        h2 = fmaxf(h2, 0.f);
        red[k] = h2 * m2W[k];
        __syncthreads();
        for (int s = 64; s > 0; s >>= 1) {
            if (k < s) red[k] += red[k + s];
            __syncthreads();
        }
        if (k == 0) g_score[hh[b] + b * Nc] = red[0] + m2b[0];
        __syncthreads();
    }
}

// ------------------------ top-K (shared-resident radix select + compaction)
//                          + fused selection / list building ------------------------
__global__ void __launch_bounds__(1024) k_topk(int l) {
    extern __shared__ unsigned char sraw[];
    unsigned* SC = (unsigned*)sraw;                       // 40000 B
    unsigned short* A  = (unsigned short*)(sraw + 40000); // 20000 B
    unsigned short* Bf = (unsigned short*)(sraw + 60000); // 20000 B
    __shared__ unsigned hist[256];
    __shared__ unsigned cum[257];
    __shared__ int sh_bsel, sh_remK, sh_cnt;

    int b = blockIdx.x, tid = threadIdx.x, lane = tid & 31;
    for (int i = tid; i < Nc; i += 1024) SC[i] = map_sc(g_score[b * Nc + i]);
    __syncthreads();

    unsigned short* cur = A;
    unsigned short* nxt = Bf;
    int candCnt = Nc;
    int remK = Kc;
    bool all = true, done = false;
    unsigned long long prefix = 0ull;
    const int shf[6] = {24, 16, 8, 0, 8, 0};   // 4 score bytes, then low-14-bit index bytes

    for (int p = 0; p < 6 && !done; p++) {
        int s = shf[p];
        bool isIdx = (p >= 4);
        if (tid < 256) hist[tid] = 0u;
        if (tid == 0) cum[256] = 0u;
        __syncthreads();

        int limit = all ? Nc : candCnt;
        int iters = (limit + 1023) >> 10;
        for (int m = 0; m < iters; m++) {
            int ii = tid + (m << 10);
            bool act = ii < limit;
            unsigned mask = __ballot_sync(0xffffffffu, act);
            if (act) {
                int i = all ? ii : (int)cur[ii];
                unsigned bin = isIdx ? (((unsigned)(Nc - 1 - i) >> s) & 255u)
                                     : ((SC[i] >> s) & 255u);
                unsigned peers = __match_any_sync(mask, bin);
                if (lane == __ffs(peers) - 1) atomicAdd(&hist[bin], (unsigned)__popc(peers));
            }
        }
        __syncthreads();

        // suffix scan: cum[t] = sum_{v>=t} hist[v]
        if (tid < 256) cum[tid] = hist[tid];
        __syncthreads();
        for (int off = 1; off < 256; off <<= 1) {
            unsigned v = 0;
            if (tid < 256 && tid + off < 256) v = cum[tid + off];
            __syncthreads();
            if (tid < 256) cum[tid] += v;
            __syncthreads();
        }
        if (tid < 256) {
            unsigned above = cum[tid + 1];
            if (cum[tid] >= (unsigned)remK && above < (unsigned)remK) {
                sh_bsel = tid;
                sh_remK = remK - (int)above;
            }
        }
        if (tid == 0) sh_cnt = 0;
        __syncthreads();
        int bsel = sh_bsel;
        int nrk = sh_remK;

        // compaction of matching candidates
        for (int m = 0; m < iters; m++) {
            int ii = tid + (m << 10);
            bool act = ii < limit;
            unsigned mask = __ballot_sync(0xffffffffu, act);
            if (act) {
                int i = all ? ii : (int)cur[ii];
                unsigned bin = isIdx ? (((unsigned)(Nc - 1 - i) >> s) & 255u)
                                     : ((SC[i] >> s) & 255u);
                bool mb = (bin == (unsigned)bsel);
                unsigned bm = __ballot_sync(mask, mb);
                if (bm) {
                    int leader = __ffs(bm) - 1;
                    int basep = 0;
                    if (lane == leader) basep = atomicAdd(&sh_cnt, (int)__popc(bm));
                    basep = __shfl_sync(mask, basep, leader);
                    if (mb) nxt[basep + __popc(bm & ((1u << lane) - 1u))] = (unsigned short)i;
                }
            }
        }
        __syncthreads();
        candCnt = sh_cnt;
        { unsigned short* t2 = cur; cur = nxt; nxt = t2; }
        all = false;
        prefix |= ((unsigned long long)(unsigned)bsel) << (isIdx ? s : (32 + s));
        remK = nrk;
        if (candCnt == remK) done = true;   // rest-of-key bytes stay zero: exact threshold
        __syncthreads();
    }

    // fused selection phase
    unsigned long long thr = prefix;
    for (int i = tid; i < Nc; i += 1024) {
        unsigned long long key = (((unsigned long long)SC[i]) << 32) | (unsigned)(Nc - 1 - i);
        int v = b * Nc + i;
        unsigned char s8 = 0;
        if (key >= thr) {
            s8 = 1;
            int od = g_outdeg[i];
            if (od > 0) {
                int p = atomicAdd(&g_UcntA[l], 1);
                g_Ulist[p] = v;
                float logd = logf((float)od + 1.f);
                atomicAdd(&g_sumlogA[l], (unsigned long long)((double)logd * 4294967296.0));
                int was = atomicExch(&g_dirty[v], 1);
                if (was) {
                    s8 = 2;                                   // Q will be valid
                    int q = atomicAdd(&g_QcntA[l], 1);
                    g_Qlist[q] = v;
                } else {
                    int p2 = atomicAdd(&g_Dcnt, 1);
                    g_Dlist[p2] = v;
                }
            }
        }
        g_sel[v] = s8;
    }
}

// ------------------------ Q fill: only selected & previously-dirty nodes ------------------------
__global__ void __launch_bounds__(128) k_qfill(int l, const float* __restrict__ Wb) {
    __shared__ float hs[Dc][8];
    __shared__ int nds[8];
    int cnt = g_QcntA[l];
    int base = blockIdx.x * 8;
    if (base >= cnt) return;
    int nt = min(8, cnt - base);
    int k = threadIdx.x;
    if (k < nt) nds[k] = g_Qlist[base + k];
    __syncthreads();
#pragma unroll
    for (int t = 0; t < 8; t++) hs[k][t] = (t < nt) ? g_hidden[nds[t] * Dc + k] : 0.f;
    __syncthreads();
    float acc[8] = {0, 0, 0, 0, 0, 0, 0, 0};
    for (int j = 0; j < Dc; j++) {
        float w = Wb[j * Dc + k];
        float4 a0 = *(const float4*)&hs[j][0];
        float4 a1 = *(const float4*)&hs[j][4];
        acc[0] = fmaf(a0.x, w, acc[0]); acc[1] = fmaf(a0.y, w, acc[1]);
        acc[2] = fmaf(a0.z, w, acc[2]); acc[3] = fmaf(a0.w, w, acc[3]);
        acc[4] = fmaf(a1.x, w, acc[4]); acc[5] = fmaf(a1.y, w, acc[5]);
        acc[6] = fmaf(a1.z, w, acc[6]); acc[7] = fmaf(a1.w, w, acc[7]);
    }
#pragma unroll
    for (int t = 0; t < 8; t++) if (t < nt) g_Q[nds[t] * Dc + k] = acc[t];
}

// ------------------------ PNA conv + residual, 16 nodes/block, 256 threads ------------------------
__global__ void __launch_bounds__(256) k_conv(int l,
                                              const float* __restrict__ preWtop,
                                              const float* __restrict__ preb,
                                              const float* __restrict__ postW,
                                              const float* __restrict__ postb,
                                              const float* __restrict__ outW,
                                              const float* __restrict__ outb) {
    extern __shared__ float cvs[];
    float* hs = cvs;            // [128][16]
    float* cs = cvs + 2048;     // [128][16]
    float* os = cvs + 4096;     // [128][16]
    float* ag = cvs + 6144;     // [512][16]
    __shared__ int un[16];
    __shared__ float d1s[16], d2s[16];

    int cnt = g_UcntA[l];
    int base = blockIdx.x * 16;
    if (base >= cnt) return;
    int nt = min(16, cnt - base);
    int tid = threadIdx.x, k = tid & 127, half = tid >> 7;

    if (tid < nt) un[tid] = g_Ulist[base + tid];
    __syncthreads();

    if (tid < 16) {
        float d1 = 0.f, d2 = 0.f;
        if (tid < nt) {
            double sl = (double)g_sumlogA[l] / 4294967296.0;
            float avl = (float)((sl + (double)(BNc - cnt) * 0.6931471805599453) / (double)BNc);
            int i = un[tid] % Nc;
            float logd = logf((float)g_outdeg[i] + 1.f);
            d1 = logd / avl;
            d2 = avl / logd;
        }
        d1s[tid] = d1; d2s[tid] = d2;
    }
#pragma unroll
    for (int j = 0; j < 8; j++) {
        int t = half * 8 + j;
        hs[k * 16 + t] = (t < nt) ? g_hidden[un[t] * Dc + k] : 0.f;
    }
    __syncthreads();

    // pre: c = hidden @ pre_W[0:D] + pre_b   (each half handles its 8 nodes)
    {
        float acc[8] = {0, 0, 0, 0, 0, 0, 0, 0};
        for (int j = 0; j < Dc; j++) {
            float w = preWtop[j * Dc + k];
            float4 a0 = *(const float4*)&hs[j * 16 + 8 * half];
            float4 a1 = *(const float4*)&hs[j * 16 + 8 * half + 4];
            acc[0] = fmaf(a0.x, w, acc[0]); acc[1] = fmaf(a0.y, w, acc[1]);
            acc[2] = fmaf(a0.z, w, acc[2]); acc[3] = fmaf(a0.w, w, acc[3]);
            acc[4] = fmaf(a1.x, w, acc[4]); acc[5] = fmaf(a1.y, w, acc[5]);
            acc[6] = fmaf(a1.z, w, acc[6]); acc[7] = fmaf(a1.w, w, acc[7]);
        }
        float pb = preb[k];
#pragma unroll
        for (int j = 0; j < 8; j++) cs[k * 16 + 8 * half + j] = acc[j] + pb;
    }
    __syncthreads();

    // aggregation: m = c_dst + Q[src] over selected in-edges
#pragma unroll
    for (int j = 0; j < 8; j++) {
        int t = 8 * half + j;
        if (t < nt) {
            int node = un[t];
            int bb = node / Nc;
            int i = node - bb * Nc;
            float c = cs[k * 16 + t];
            float s1 = 0.f, s2 = 0.f;
            float mx = -INFINITY, mn = INFINITY;
            int ce = 0;
            int e0 = g_inoff[i], e1 = g_inoff[i + 1];
            for (int e = e0; e < e1; e++) {
                int sg = bb * Nc + g_insrc[e];
                unsigned char sv = g_sel[sg];
                if (sv) {
                    float m = c + (sv == 2 ? g_Q[sg * Dc + k] : 0.f);
                    s1 += m; s2 += m * m;
                    mx = fmaxf(mx, m); mn = fminf(mn, m);
                    ce++;
                }
            }
            float denom = (float)max(ce, 1);
            float mean = s1 / denom;
            float var = fmaxf(s2 / denom - mean * mean, 0.f);
            float st = sqrtf(var + EPSc);
            if (ce == 0) { mx = 0.f; mn = 0.f; }
            ag[k * 16 + t] = mean;
            ag[(128 + k) * 16 + t] = mx;
            ag[(256 + k) * 16 + t] = mn;
            ag[(384 + k) * 16 + t] = st;
        } else {
            ag[k * 16 + t] = 0.f;
            ag[(128 + k) * 16 + t] = 0.f;
            ag[(256 + k) * 16 + t] = 0.f;
            ag[(384 + k) * 16 + t] = 0.f;
        }
    }
    __syncthreads();

    // post: agg12 @ post_W + post_b with the degree scalers folded into weights
    {
        float d1r[8], d2r[8];
#pragma unroll
        for (int j = 0; j < 8; j++) { d1r[j] = d1s[8 * half + j]; d2r[j] = d2s[8 * half + j]; }
        float ac2[8] = {0, 0, 0, 0, 0, 0, 0, 0};
        for (int j = 0; j < 512; j++) {
            float w0 = postW[j * Dc + k];
            float w1 = postW[(512 + j) * Dc + k];
            float w2 = postW[(1024 + j) * Dc + k];
            float4 a0 = *(const float4*)&ag[j * 16 + 8 * half];
            float4 a1 = *(const float4*)&ag[j * 16 + 8 * half + 4];
            float av[8] = {a0.x, a0.y, a0.z, a0.w, a1.x, a1.y, a1.z, a1.w};
#pragma unroll
            for (int t = 0; t < 8; t++) {
                float wt = fmaf(d1r[t], w1, fmaf(d2r[t], w2, w0));
                ac2[t] = fmaf(av[t], wt, ac2[t]);
            }
        }
        float pob = postb[k];
#pragma unroll
        for (int j = 0; j < 8; j++) os[k * 16 + 8 * half + j] = ac2[j] + pob;
    }
    __syncthreads();

    // out: out1 @ out_W + out_b; residual add
    {
        float ac3[8] = {0, 0, 0, 0, 0, 0, 0, 0};
        for (int j = 0; j < Dc; j++) {
            float w = outW[j * Dc + k];
            float4 a0 = *(const float4*)&os[j * 16 + 8 * half];
            float4 a1 = *(const float4*)&os[j * 16 + 8 * half + 4];
            ac3[0] = fmaf(a0.x, w, ac3[0]); ac3[1] = fmaf(a0.y, w, ac3[1]);
            ac3[2] = fmaf(a0.z, w, ac3[2]); ac3[3] = fmaf(a0.w, w, ac3[3]);
            ac3[4] = fmaf(a1.x, w, ac3[4]); ac3[5] = fmaf(a1.y, w, ac3[5]);
            ac3[6] = fmaf(a1.z, w, ac3[6]); ac3[7] = fmaf(a1.w, w, ac3[7]);
        }
        float ob = outb[k];
#pragma unroll
        for (int j = 0; j < 8; j++) {
            int t = 8 * half + j;
            if (t < nt) g_hidden[un[t] * Dc + k] += ac3[j] + ob;
        }
    }
}

// ------------------------ scoring (mode 0: Dlist + clean fill; 1: Ulist; 2: readout) ----------
__global__ void __launch_bounds__(128) k_score(int mode,
                                               const float* __restrict__ linW,
                                               const float* __restrict__ m1W,
                                               const float* __restrict__ m1b,
                                               const float* __restrict__ m2W,
                                               const float* __restrict__ m2b,
                                               float* __restrict__ out) {
    int blk = blockIdx.x;
    int k = threadIdx.x;
    if (mode == 0 && blk >= SCORE_BLKS) {
        int j = (blk - SCORE_BLKS) * 128 + k;
        if (j < BNc && g_dirty[j] == 0) g_score[j] = g_szero;
        return;
    }
    const int* list;
    int cnt;
    if (mode == 0)      { list = g_Dlist; cnt = g_Dcnt; }
    else if (mode == 1) { list = g_Ulist; cnt = g_UcntA[1]; }
    else                { list = g_tidx;  cnt = Bc * NEGc; }

    int base = blk * 8;
    if (base >= cnt) return;
    int nt = min(8, cnt - base);

    __shared__ float hs[Dc][8];
    __shared__ float xs[Dc][8];
    __shared__ float red[Dc][8];
    __shared__ int nds[8];
    if (k < nt) nds[k] = list[base + k];
    __syncthreads();
#pragma unroll
    for (int t = 0; t < 8; t++) hs[k][t] = (t < nt) ? g_hidden[nds[t] * Dc + k] : 0.f;
    __syncthreads();

    float acc[8] = {0, 0, 0, 0, 0, 0, 0, 0};
    for (int j = 0; j < Dc; j++) {
        float w = linW[j * Dc + k];
        float4 a0 = *(const float4*)&hs[j][0];
        float4 a1 = *(const float4*)&hs[j][4];
        acc[0] = fmaf(a0.x, w, acc[0]); acc[1] = fmaf(a0.y, w, acc[1]);
        acc[2] = fmaf(a0.z, w, acc[2]); acc[3] = fmaf(a0.w, w, acc[3]);
        acc[4] = fmaf(a1.x, w, acc[4]); acc[5] = fmaf(a1.y, w, acc[5]);
        acc[6] = fmaf(a1.z, w, acc[6]); acc[7] = fmaf(a1.w, w, acc[7]);
    }
#pragma unroll
    for (int t = 0; t < 8; t++) {
        float x = 0.f;
        if (t < nt) {
            int bb = nds[t] / Nc;
            x = (acc[t] + g_rellin[bb * Dc + k]) * hs[k][t];
        }
        xs[k][t] = x;
    }
    __syncthreads();

    float ac2[8] = {0, 0, 0, 0, 0, 0, 0, 0};
    for (int j = 0; j < Dc; j++) {
        float w = m1W[j * Dc + k];
        float4 a0 = *(const float4*)&xs[j][0];
        float4 a1 = *(const float4*)&xs[j][4];
        ac2[0] = fmaf(a0.x, w, ac2[0]); ac2[1] = fmaf(a0.y, w, ac2[1]);
        ac2[2] = fmaf(a0.z, w, ac2[2]); ac2[3] = fmaf(a0.w, w, ac2[3]);
        ac2[4] = fmaf(a1.x, w, ac2[4]); ac2[5] = fmaf(a1.y, w, ac2[5]);
        ac2[6] = fmaf(a1.z, w, ac2[6]); ac2[7] = fmaf(a1.w, w, ac2[7]);
    }
    float mb = m1b[k], w2 = m2W[k];
#pragma unroll
    for (int t = 0; t < 8; t++) red[k][t] = fmaxf(ac2[t] + mb, 0.f) * w2;
    __syncthreads();
    for (int s = 64; s > 0; s >>= 1) {
        if (k < s) {
#pragma unroll
            for (int t = 0; t < 8; t++) red[k][t] += red[k + s][t];
        }
        __syncthreads();
    }
    if (k < nt) {
        float r = red[0][k] + m2b[0];
        if (mode == 2) out[base + k] = r;
        else g_score[nds[k]] = r;
    }
}

// ------------------------ state restoration (replaces bulk zeroing) ------------------------
__global__ void __launch_bounds__(128) k_cleanup() {
    int blk = blockIdx.x, k = threadIdx.x;
    if (blk < SCORE_BLKS) {
        int cnt = g_Dcnt;
        int base = blk * 8;
        if (base >= cnt) return;
        int nt = min(8, cnt - base);
        __shared__ int nds[8];
        if (k < nt) nds[k] = g_Dlist[base + k];
        __syncthreads();
        for (int t = 0; t < nt; t++) g_hidden[nds[t] * Dc + k] = 0.f;
        if (k < nt) g_dirty[nds[k]] = 0;
    } else {
        int j = (blk - SCORE_BLKS) * 128 + k;
        if (j < BNc) g_score[j] = 0.f;
        if (j < Nc) { g_outdeg[j] = 0; g_indeg[j] = 0; }
    }
}

__global__ void k_reset() {
    int t = threadIdx.x;
    if (t == 0) g_Dcnt = 0;
    if (t < Lc) { g_UcntA[t] = 0; g_QcntA[t] = 0; g_sumlogA[t] = 0ull; }
}

// ------------------------ host ------------------------
extern "C" void kernel_launch(void* const* d_in, const int* in_sizes, int n_in,
                              void* d_out, int out_size) {
    const int*   hI    = (const int*)d_in[0];
    const int*   rI    = (const int*)d_in[1];
    const int*   tI    = (const int*)d_in[2];
    const float* HS    = (const float*)d_in[3];
    const int*   EI    = (const int*)d_in[4];
    const float* RE    = (const float*)d_in[5];
    const float* linW  = (const float*)d_in[6];
    const float* linb  = (const float*)d_in[7];
    const float* m1W   = (const float*)d_in[8];
    const float* m1b   = (const float*)d_in[9];
    const float* m2W   = (const float*)d_in[10];
    const float* m2b   = (const float*)d_in[11];
    const float* preW  = (const float*)d_in[12];
    const float* preb  = (const float*)d_in[13];
    const float* postW = (const float*)d_in[14];
    const float* postb = (const float*)d_in[15];
    const float* outW  = (const float*)d_in[16];
    const float* outb  = (const float*)d_in[17];
    float* out = (float*)d_out;

    cudaFuncSetAttribute(k_topk, cudaFuncAttributeMaxDynamicSharedMemorySize, 80000);
    cudaFuncSetAttribute(k_conv, cudaFuncAttributeMaxDynamicSharedMemorySize, 57344);

    k_deg<<<(Ec + 255) / 256, 256>>>(EI);
    k_scan<<<1, 1024>>>();
    k_fill<<<(Ec + 255) / 256, 256>>>(EI);
    k_prep<<<1, 128>>>(hI, rI, tI, HS, RE, linW, linb, m1W, m1b, m2W, m2b);

    for (int l = 0; l < Lc; l++) {
        k_topk<<<Bc, 1024, 80000>>>(l);
        k_qfill<<<UMAXc / 8, 128>>>(l, preW + l * 2 * Dc * Dc + Dc * Dc);
        k_conv<<<UMAXc / 16, 256, 57344>>>(l, preW + l * 2 * Dc * Dc, preb + l * Dc,
                                           postW + l * 12 * Dc * Dc, postb + l * Dc,
                                           outW + l * Dc * Dc, outb + l * Dc);
        if (l == 0)
            k_score<<<SCORE_BLKS + FILL_BLKS, 128>>>(0, linW, m1W, m1b, m2W, m2b, out);
        else if (l == 1)
            k_score<<<UMAXc / 8, 128>>>(1, linW, m1W, m1b, m2W, m2b, out);
        else
            k_score<<<(Bc * NEGc + 7) / 8, 128>>>(2, linW, m1W, m1b, m2W, m2b, out);
    }

    k_cleanup<<<SCORE_BLKS + FILL_BLKS, 128>>>();
    k_reset<<<1, 32>>>();
}

// round 7
// speedup vs baseline: 1.8079x; 1.8079x over previous
#include <cuda_runtime.h>
#include <math.h>

// ------------------------ problem constants ------------------------
#define Bc      2
#define NEGc    16
#define Nc      10000
#define Ec      80000
#define Dc      128
#define Lc      3
#define Kc      1000
#define BNc     20000
#define NUMRELc 237
#define EPSc    1e-5f
#define DMAXc   6016     // max dirty nodes: 4 boundary + 3*2000
#define UMAXc   2048     // max updated nodes per layer (<= B*K = 2000)

// ------------------------ device scratch (static, no runtime alloc) ------------------------
__device__ float g_hidden[BNc * Dc];
__device__ float g_Q[BNc * Dc];
__device__ float g_score[BNc];
__device__ int   g_dirty[BNc];
__device__ unsigned char g_sel[BNc];
__device__ int   g_indeg[Nc];
__device__ int   g_outdeg[Nc];
__device__ int   g_inoff[Nc + 1];
__device__ int   g_cursor[Nc];
__device__ int   g_insrc[Ec];
__device__ int   g_Dlist[DMAXc];
__device__ int   g_Dcnt;
__device__ int   g_Ulist[UMAXc];
__device__ int   g_Ucnt;
__device__ unsigned long long g_sumlog;
__device__ unsigned long long g_thr[Bc];
__device__ float g_rel[Bc * Dc];
__device__ float g_rellin[Bc * Dc];
__device__ float g_szero;
__device__ int   g_tidx[Bc * NEGc];

// ------------------------ helpers ------------------------
__device__ __forceinline__ unsigned map_sc(float f) {
    unsigned u = __float_as_uint(f);
    if (u == 0x80000000u) u = 0u;                      // normalize -0 -> +0
    return (u & 0x80000000u) ? ~u : (u | 0x80000000u); // monotone order-preserving map
}

__device__ __forceinline__ unsigned long long make_key(float f, int i) {
    return (((unsigned long long)map_sc(f)) << 32) | (unsigned)(Nc - 1 - i);
}

// ------------------------ init ------------------------
__global__ void k_zero() {
    int i = blockIdx.x * 256 + threadIdx.x;
    if (i < BNc * Dc) { g_hidden[i] = 0.f; g_Q[i] = 0.f; }
    if (i < BNc)      { g_score[i] = 0.f; g_dirty[i] = 0; g_sel[i] = 0; }
    if (i < Nc)       { g_indeg[i] = 0; g_outdeg[i] = 0; }
    if (i == 0)       { g_Dcnt = 0; }
}

__global__ void k_deg(const int* __restrict__ ei) {
    int i = blockIdx.x * 256 + threadIdx.x;
    if (i < Ec) {
        atomicAdd(&g_outdeg[ei[i]], 1);
        atomicAdd(&g_indeg[ei[Ec + i]], 1);
    }
}

__global__ void k_scan() {   // exclusive scan of indeg -> inoff (single block, 1024 thr)
    __shared__ int tot[1024];
    int t = threadIdx.x;
    const int CH = 10;
    int loc[CH];
    int s = 0;
#pragma unroll
    for (int j = 0; j < CH; j++) {
        int idx = t * CH + j;
        int v = (idx < Nc) ? g_indeg[idx] : 0;
        loc[j] = s; s += v;
    }
    tot[t] = s;
    __syncthreads();
    for (int off = 1; off < 1024; off <<= 1) {
        int v = (t >= off) ? tot[t - off] : 0;
        __syncthreads();
        tot[t] += v;
        __syncthreads();
    }
    int ex = tot[t] - s;
#pragma unroll
    for (int j = 0; j < CH; j++) {
        int idx = t * CH + j;
        if (idx < Nc) { g_inoff[idx] = ex + loc[j]; g_cursor[idx] = 0; }
    }
    if (t == 1023) g_inoff[Nc] = tot[1023];
}

__global__ void k_fill(const int* __restrict__ ei) {
    int i = blockIdx.x * 256 + threadIdx.x;
    if (i < Ec) {
        int d = ei[Ec + i];
        int pos = atomicAdd(&g_cursor[d], 1);
        g_insrc[g_inoff[d] + pos] = ei[i];
    }
}

// ------------------------ prep phase 1: misc + rel_lin (3 blocks) ------------------------
__global__ void __launch_bounds__(128) k_prep1(const int* __restrict__ hI, const int* __restrict__ rI,
                        const int* __restrict__ tI, const float* __restrict__ HS,
                        const float* __restrict__ RE, const float* __restrict__ linW,
                        const float* __restrict__ linb, const float* __restrict__ m1b,
                        const float* __restrict__ m2W, const float* __restrict__ m2b) {
    int k = threadIdx.x, blk = blockIdx.x;
    __shared__ int hh[Bc], tt[Bc], rr[Bc], isT[Bc];
    __shared__ float rl[Dc];
    __shared__ float red[Dc];

    if (k < Bc) {
        int b = k;
        int t_neg = 1;
        int h0 = hI[b * NEGc];
        for (int j = 1; j < NEGc; j++) if (hI[b * NEGc + j] != h0) t_neg = 0;
        isT[b] = t_neg;
        hh[b] = t_neg ? h0 : tI[b * NEGc];
        tt[b] = t_neg ? tI[b * NEGc] : h0;
        rr[b] = t_neg ? rI[b * NEGc] : (rI[b * NEGc] + NUMRELc);
    }
    __syncthreads();

    if (blk == 0) {
        // readout indices
        for (int idx = k; idx < Bc * NEGc; idx += Dc) {
            int b = idx / NEGc;
            int tv = isT[b] ? tI[idx] : hI[idx];
            g_tidx[idx] = tv + b * Nc;
        }
        // rel embeddings
        for (int b = 0; b < Bc; b++) g_rel[b * Dc + k] = RE[rr[b] * Dc + k];
        // reference quirk: h_vals/t_vals both use ROW 0's indices for every batch
        float hv = HS[hh[0] * Dc + k];
        float tv = HS[tt[0] * Dc + k];
        for (int b = 0; b < Bc; b++) g_hidden[(tt[b] + b * Nc) * Dc + k] = tv;
        __syncthreads();
        for (int b = 0; b < Bc; b++) g_hidden[(hh[b] + b * Nc) * Dc + k] = hv;
        if (k == 0) {
            for (int b = 0; b < Bc; b++) {
                int nodes2[2] = { tt[b] + b * Nc, hh[b] + b * Nc };
                for (int q = 0; q < 2; q++) {
                    int v = nodes2[q];
                    if (atomicExch(&g_dirty[v], 1) == 0) {
                        int p = atomicAdd(&g_Dcnt, 1);
                        g_Dlist[p] = v;
                    }
                }
            }
        }
        // s_zero = relu(m1_b) @ m2_W + m2_b
        red[k] = fmaxf(m1b[k], 0.f) * m2W[k];
        __syncthreads();
        for (int s = 64; s > 0; s >>= 1) {
            if (k < s) red[k] += red[k + s];
            __syncthreads();
        }
        if (k == 0) g_szero = red[0] + m2b[0];
    } else {
        int b = blk - 1;
        rl[k] = RE[rr[b] * Dc + k];
        __syncthreads();
        float a = linb[k];
#pragma unroll 8
        for (int j = 0; j < Dc; j++) a += rl[j] * linW[(Dc + j) * Dc + k];
        g_rellin[b * Dc + k] = a;
    }
}

// ------------------------ prep phase 2: initial score per batch (2 blocks) ------------------------
__global__ void __launch_bounds__(128) k_prep2(const int* __restrict__ hI, const int* __restrict__ tI,
                        const float* __restrict__ HS, const float* __restrict__ linW,
                        const float* __restrict__ m1W, const float* __restrict__ m1b,
                        const float* __restrict__ m2W, const float* __restrict__ m2b) {
    int k = threadIdx.x, b = blockIdx.x;
    __shared__ float hvs[Dc], xs[Dc], red[Dc];

    // hh[0] (embedding row, quirk) and hh[b] (write position)
    int tn0 = 1, h00 = hI[0];
    for (int j = 1; j < NEGc; j++) if (hI[j] != h00) tn0 = 0;
    int hh0 = tn0 ? h00 : tI[0];
    int tnb = 1, hb0 = hI[b * NEGc];
    for (int j = 1; j < NEGc; j++) if (hI[b * NEGc + j] != hb0) tnb = 0;
    int hhb = tnb ? hb0 : tI[b * NEGc];

    float hv = HS[hh0 * Dc + k];
    hvs[k] = hv;
    __syncthreads();

    float a = g_rellin[b * Dc + k];
#pragma unroll 8
    for (int j = 0; j < Dc; j++) a += hvs[j] * linW[j * Dc + k];
    float x = a * hv;
    xs[k] = x;
    __syncthreads();
    float h2 = m1b[k];
#pragma unroll 8
    for (int j = 0; j < Dc; j++) h2 += xs[j] * m1W[j * Dc + k];
    h2 = fmaxf(h2, 0.f);
    red[k] = h2 * m2W[k];
    __syncthreads();
    for (int s = 64; s > 0; s >>= 1) {
        if (k < s) red[k] += red[k + s];
        __syncthreads();
    }
    if (k == 0) g_score[hhb + b * Nc] = red[0] + m2b[0];
}

// ------------------------ exact top-K threshold (shared-cached radix select) ------------------------
__global__ void __launch_bounds__(1024) k_topk() {
    extern __shared__ unsigned SC[];            // Nc mapped scores (40000 B)
    __shared__ unsigned hist[256];
    __shared__ unsigned cum[257];
    __shared__ int sh_bsel, sh_remK, sh_done;

    int b = blockIdx.x, tid = threadIdx.x, lane = tid & 31;
    if (b == 0 && tid == 0) { g_Ucnt = 0; g_sumlog = 0ull; }
    for (int i = tid; i < Nc; i += 1024) SC[i] = map_sc(g_score[b * Nc + i]);
    if (tid == 0) { sh_remK = Kc; sh_done = 0; }
    __syncthreads();

    unsigned long long prefix = 0ull;
    const int S[6] = {56, 48, 40, 32, 8, 0};   // key byte positions (idx bytes 24,16 always 0)

    for (int p = 0; p < 6; p++) {
        if (sh_done) break;
        if (tid < 256) hist[tid] = 0u;
        __syncthreads();
        int remK = sh_remK;

        for (int m = 0; m < 10; m++) {
            int i = tid + (m << 10);
            bool act = (i < Nc);
            unsigned bin = 0;
            bool match = false;
            if (act) {
                unsigned long long key = (((unsigned long long)SC[i]) << 32) | (unsigned)(Nc - 1 - i);
                match = (p == 0) || ((key >> (S[p] + 8)) == (prefix >> (S[p] + 8)));
                bin = (unsigned)((key >> S[p]) & 255ull);
            }
            unsigned am = __ballot_sync(0xffffffffu, act && match);
            if (act && match) {
                unsigned peers = __match_any_sync(am, bin);
                if (lane == __ffs(peers) - 1) atomicAdd(&hist[bin], (unsigned)__popc(peers));
            }
        }
        __syncthreads();

        // suffix scan: cum[t] = sum_{v>=t} hist[v]
        if (tid < 256) cum[tid] = hist[tid];
        if (tid == 0) cum[256] = 0u;
        __syncthreads();
        for (int off = 1; off < 256; off <<= 1) {
            unsigned v = 0;
            if (tid < 256 && tid + off < 256) v = cum[tid + off];
            __syncthreads();
            if (tid < 256) cum[tid] += v;
            __syncthreads();
        }
        if (tid < 256) {
            unsigned above = (tid == 255) ? 0u : cum[tid + 1];
            if (cum[tid] >= (unsigned)remK && above < (unsigned)remK) sh_bsel = tid;
        }
        __syncthreads();
        int bsel = sh_bsel;
        prefix |= ((unsigned long long)(unsigned)bsel) << S[p];
        if (tid == 0) {
            unsigned above = (bsel == 255) ? 0u : cum[bsel + 1];
            int newRem = remK - (int)above;
            sh_remK = newRem;
            if ((int)hist[bsel] == newRem) sh_done = 1;  // whole bin selected: lower bytes stay 0
        }
        __syncthreads();
    }
    if (tid == 0) g_thr[b] = prefix;
}

// ------------------------ selection + lists (warp-aggregated atomics) ------------------------
__global__ void k_select() {
    int v = blockIdx.x * 256 + threadIdx.x;
    if (v >= BNc) return;          // BNc % 32 == 0 -> warps fully active or fully returned
    int b = v / Nc;
    int i = v - b * Nc;
    unsigned long long key = make_key(g_score[v], i);
    bool s = (key >= g_thr[b]);
    g_sel[v] = s ? (unsigned char)1 : (unsigned char)0;
    int od = g_outdeg[i];
    bool upd = s && (od > 0);
    int lane = threadIdx.x & 31;

    // warp-aggregated sumlog (fixed-point, order-independent)
    unsigned long long contrib = 0ull;
    if (upd) contrib = (unsigned long long)((double)logf((float)od + 1.f) * 4294967296.0);
#pragma unroll
    for (int off = 16; off > 0; off >>= 1)
        contrib += __shfl_down_sync(0xffffffffu, contrib, off);
    if (lane == 0 && contrib) atomicAdd(&g_sumlog, contrib);

    // warp-aggregated Ulist append
    unsigned um = __ballot_sync(0xffffffffu, upd);
    if (um) {
        int leader = __ffs(um) - 1;
        int baseU = 0;
        if (lane == leader) baseU = atomicAdd(&g_Ucnt, __popc(um));
        baseU = __shfl_sync(0xffffffffu, baseU, leader);
        if (upd) {
            int pos = baseU + __popc(um & ((1u << lane) - 1u));
            g_Ulist[pos] = v;
            if (atomicExch(&g_dirty[v], 1) == 0) {
                int p2 = atomicAdd(&g_Dcnt, 1);
                g_Dlist[p2] = v;
            }
        }
    }
}

// ------------------------ Q fill: Q[v] = hidden[v] @ pre_W[D:2D]  (dirty nodes, 8/block) ------------------------
__global__ void __launch_bounds__(128) k_qfill(const float* __restrict__ Wb) {
    __shared__ float hs[Dc][8];
    __shared__ int nds[8];
    int base = blockIdx.x * 8;
    int cnt = g_Dcnt;
    if (base >= cnt) return;
    int nt = min(8, cnt - base);
    int k = threadIdx.x;
    if (k < nt) nds[k] = g_Dlist[base + k];
    __syncthreads();
#pragma unroll
    for (int t = 0; t < 8; t++) hs[k][t] = (t < nt) ? g_hidden[nds[t] * Dc + k] : 0.f;
    __syncthreads();
    float acc[8] = {0, 0, 0, 0, 0, 0, 0, 0};
    for (int j = 0; j < Dc; j++) {
        float w = Wb[j * Dc + k];
        float4 a0 = *(const float4*)&hs[j][0];
        float4 a1 = *(const float4*)&hs[j][4];
        acc[0] = fmaf(a0.x, w, acc[0]); acc[1] = fmaf(a0.y, w, acc[1]);
        acc[2] = fmaf(a0.z, w, acc[2]); acc[3] = fmaf(a0.w, w, acc[3]);
        acc[4] = fmaf(a1.x, w, acc[4]); acc[5] = fmaf(a1.y, w, acc[5]);
        acc[6] = fmaf(a1.z, w, acc[6]); acc[7] = fmaf(a1.w, w, acc[7]);
    }
#pragma unroll
    for (int t = 0; t < 8; t++) if (t < nt) g_Q[nds[t] * Dc + k] = acc[t];
}

// ------------------------ PNA conv + residual at U nodes (8/block), avg_log inline ------------------------
__global__ void __launch_bounds__(128) k_conv(const float* __restrict__ preWtop,
                                              const float* __restrict__ preb,
                                              const float* __restrict__ postW,
                                              const float* __restrict__ postb,
                                              const float* __restrict__ outW,
                                              const float* __restrict__ outb) {
    __shared__ float hs[Dc][8];
    __shared__ float cs[Dc][8];
    __shared__ float aggs[512][8];   // base agg: [mean | max | min | std]
    __shared__ float os[Dc][8];
    __shared__ float d1s[8], d2s[8];
    __shared__ int un[8];

    int base = blockIdx.x * 8;
    int cnt = g_Ucnt;
    if (base >= cnt) return;
    int nt = min(8, cnt - base);
    int k = threadIdx.x;
    if (k < nt) un[k] = g_Ulist[base + k];
    __syncthreads();
#pragma unroll
    for (int t = 0; t < 8; t++) hs[k][t] = (t < nt) ? g_hidden[un[t] * Dc + k] : 0.f;
    if (k < 8) {
        float d1 = 0.f, d2 = 0.f;
        if (k < nt) {
            double sl = (double)g_sumlog / 4294967296.0;
            float avl = (float)((sl + (double)(BNc - cnt) * 0.6931471805599453) / (double)BNc);
            int node = un[k];
            int i = node % Nc;
            float logd = logf((float)g_outdeg[i] + 1.f);
            d1 = logd / avl;
            d2 = avl / logd;
        }
        d1s[k] = d1; d2s[k] = d2;
    }
    __syncthreads();

    // P(u) = hidden[u] @ pre_W[0:D]; c = P + pre_b
    {
        float acc[8] = {0, 0, 0, 0, 0, 0, 0, 0};
        for (int j = 0; j < Dc; j++) {
            float w = preWtop[j * Dc + k];
            float4 a0 = *(const float4*)&hs[j][0];
            float4 a1 = *(const float4*)&hs[j][4];
            acc[0] = fmaf(a0.x, w, acc[0]); acc[1] = fmaf(a0.y, w, acc[1]);
            acc[2] = fmaf(a0.z, w, acc[2]); acc[3] = fmaf(a0.w, w, acc[3]);
            acc[4] = fmaf(a1.x, w, acc[4]); acc[5] = fmaf(a1.y, w, acc[5]);
            acc[6] = fmaf(a1.z, w, acc[6]); acc[7] = fmaf(a1.w, w, acc[7]);
        }
        float pb = preb[k];
#pragma unroll
        for (int t = 0; t < 8; t++) cs[k][t] = acc[t] + pb;
    }
    __syncthreads();

    // aggregation per node over selected in-edges: m = c + Q[src]
    for (int t = 0; t < nt; t++) {
        int node = un[t];
        int b = node / Nc;
        int i = node - b * Nc;
        float c = cs[k][t];
        float s1 = 0.f, s2 = 0.f;
        float mx = -INFINITY, mn = INFINITY;
        int ce = 0;
        int e0 = g_inoff[i], e1 = g_inoff[i + 1];
        for (int e = e0; e < e1; e++) {
            int sg = b * Nc + g_insrc[e];
            if (g_sel[sg]) {
                float m = c + g_Q[sg * Dc + k];
                s1 += m; s2 += m * m;
                mx = fmaxf(mx, m); mn = fminf(mn, m);
                ce++;
            }
        }
        float denom = (float)max(ce, 1);
        float mean = s1 / denom;
        float var = fmaxf(s2 / denom - mean * mean, 0.f);
        float st = sqrtf(var + EPSc);
        if (ce == 0) { mx = 0.f; mn = 0.f; }
        aggs[k][t] = mean;
        aggs[128 + k][t] = mx;
        aggs[256 + k][t] = mn;
        aggs[384 + k][t] = st;
    }
    for (int t = nt; t < 8; t++) {
        aggs[k][t] = 0.f; aggs[128 + k][t] = 0.f;
        aggs[256 + k][t] = 0.f; aggs[384 + k][t] = 0.f;
    }
    __syncthreads();

    // out1 = agg12 @ post_W + post_b, with scalers folded into the weight read
    {
        float d1r[8], d2r[8];
#pragma unroll
        for (int t = 0; t < 8; t++) { d1r[t] = d1s[t]; d2r[t] = d2s[t]; }
        float ac2[8] = {0, 0, 0, 0, 0, 0, 0, 0};
        for (int j = 0; j < 512; j++) {
            float w0 = postW[j * Dc + k];
            float w1 = postW[(512 + j) * Dc + k];
            float w2 = postW[(1024 + j) * Dc + k];
            float4 a0 = *(const float4*)&aggs[j][0];
            float4 a1 = *(const float4*)&aggs[j][4];
            float av[8] = {a0.x, a0.y, a0.z, a0.w, a1.x, a1.y, a1.z, a1.w};
#pragma unroll
            for (int t = 0; t < 8; t++) {
                float wt = fmaf(d1r[t], w1, fmaf(d2r[t], w2, w0));
                ac2[t] = fmaf(av[t], wt, ac2[t]);
            }
        }
        float pob = postb[k];
#pragma unroll
        for (int t = 0; t < 8; t++) os[k][t] = ac2[t] + pob;
    }
    __syncthreads();

    // out2 = out1 @ out_W + out_b; hidden[u] += out2
    {
        float ac3[8] = {0, 0, 0, 0, 0, 0, 0, 0};
        for (int j = 0; j < Dc; j++) {
            float w = outW[j * Dc + k];
            float4 a0 = *(const float4*)&os[j][0];
            float4 a1 = *(const float4*)&os[j][4];
            ac3[0] = fmaf(a0.x, w, ac3[0]); ac3[1] = fmaf(a0.y, w, ac3[1]);
            ac3[2] = fmaf(a0.z, w, ac3[2]); ac3[3] = fmaf(a0.w, w, ac3[3]);
            ac3[4] = fmaf(a1.x, w, ac3[4]); ac3[5] = fmaf(a1.y, w, ac3[5]);
            ac3[6] = fmaf(a1.z, w, ac3[6]); ac3[7] = fmaf(a1.w, w, ac3[7]);
        }
        float ob = outb[k];
        for (int t = 0; t < nt; t++) g_hidden[un[t] * Dc + k] += ac3[t] + ob;
    }
}

// ------------------------ rescore ------------------------
__global__ void k_fillscore() {
    int v = blockIdx.x * 256 + threadIdx.x;
    if (v < BNc) g_score[v] = g_szero;
}

__global__ void __launch_bounds__(128) k_score(const float* __restrict__ linW,
                                               const float* __restrict__ m1W,
                                               const float* __restrict__ m1b,
                                               const float* __restrict__ m2W,
                                               const float* __restrict__ m2b) {
    __shared__ float hs[Dc][8];
    __shared__ float xs[Dc][8];
    __shared__ float red[Dc][8];
    __shared__ int nds[8];
    int base = blockIdx.x * 8;
    int cnt = g_Dcnt;
    if (base >= cnt) return;
    int nt = min(8, cnt - base);
    int k = threadIdx.x;
    if (k < nt) nds[k] = g_Dlist[base + k];
    __syncthreads();
#pragma unroll
    for (int t = 0; t < 8; t++) hs[k][t] = (t < nt) ? g_hidden[nds[t] * Dc + k] : 0.f;
    __syncthreads();

    float acc[8] = {0, 0, 0, 0, 0, 0, 0, 0};
    for (int j = 0; j < Dc; j++) {
        float w = linW[j * Dc + k];
        float4 a0 = *(const float4*)&hs[j][0];
        float4 a1 = *(const float4*)&hs[j][4];
        acc[0] = fmaf(a0.x, w, acc[0]); acc[1] = fmaf(a0.y, w, acc[1]);
        acc[2] = fmaf(a0.z, w, acc[2]); acc[3] = fmaf(a0.w, w, acc[3]);
        acc[4] = fmaf(a1.x, w, acc[4]); acc[5] = fmaf(a1.y, w, acc[5]);
        acc[6] = fmaf(a1.z, w, acc[6]); acc[7] = fmaf(a1.w, w, acc[7]);
    }
#pragma unroll
    for (int t = 0; t < 8; t++) {
        float x = 0.f;
        if (t < nt) {
            int bb = nds[t] / Nc;
            x = (acc[t] + g_rellin[bb * Dc + k]) * hs[k][t];
        }
        xs[k][t] = x;
    }
    __syncthreads();

    float ac2[8] = {0, 0, 0, 0, 0, 0, 0, 0};
    for (int j = 0; j < Dc; j++) {
        float w = m1W[j * Dc + k];
        float4 a0 = *(const float4*)&xs[j][0];
        float4 a1 = *(const float4*)&xs[j][4];
        ac2[0] = fmaf(a0.x, w, ac2[0]); ac2[1] = fmaf(a0.y, w, ac2[1]);
        ac2[2] = fmaf(a0.z, w, ac2[2]); ac2[3] = fmaf(a0.w, w, ac2[3]);
        ac2[4] = fmaf(a1.x, w, ac2[4]); ac2[5] = fmaf(a1.y, w, ac2[5]);
        ac2[6] = fmaf(a1.z, w, ac2[6]); ac2[7] = fmaf(a1.w, w, ac2[7]);
    }
    float mb = m1b[k], w2 = m2W[k];
#pragma unroll
    for (int t = 0; t < 8; t++) red[k][t] = fmaxf(ac2[t] + mb, 0.f) * w2;
    __syncthreads();
    for (int s = 64; s > 0; s >>= 1) {
        if (k < s) {
#pragma unroll
            for (int t = 0; t < 8; t++) red[k][t] += red[k + s][t];
        }
        __syncthreads();
    }
    if (k < nt) g_score[nds[k]] = red[0][k] + m2b[0];
}

// ------------------------ readout ------------------------
__global__ void k_readout(float* __restrict__ out) {
    int i = threadIdx.x;
    if (i < Bc * NEGc) out[i] = g_score[g_tidx[i]];
}

// ------------------------ host ------------------------
extern "C" void kernel_launch(void* const* d_in, const int* in_sizes, int n_in,
                              void* d_out, int out_size) {
    const int*   hI    = (const int*)d_in[0];
    const int*   rI    = (const int*)d_in[1];
    const int*   tI    = (const int*)d_in[2];
    const float* HS    = (const float*)d_in[3];
    const int*   EI    = (const int*)d_in[4];
    const float* RE    = (const float*)d_in[5];
    const float* linW  = (const float*)d_in[6];
    const float* linb  = (const float*)d_in[7];
    const float* m1W   = (const float*)d_in[8];
    const float* m1b   = (const float*)d_in[9];
    const float* m2W   = (const float*)d_in[10];
    const float* m2b   = (const float*)d_in[11];
    const float* preW  = (const float*)d_in[12];
    const float* preb  = (const float*)d_in[13];
    const float* postW = (const float*)d_in[14];
    const float* postb = (const float*)d_in[15];
    const float* outW  = (const float*)d_in[16];
    const float* outb  = (const float*)d_in[17];
    float* out = (float*)d_out;

    k_zero<<<(BNc * Dc + 255) / 256, 256>>>();
    k_deg<<<(Ec + 255) / 256, 256>>>(EI);
    k_scan<<<1, 1024>>>();
    k_fill<<<(Ec + 255) / 256, 256>>>(EI);
    k_prep1<<<3, 128>>>(hI, rI, tI, HS, RE, linW, linb, m1b, m2W, m2b);
    k_prep2<<<2, 128>>>(hI, tI, HS, linW, m1W, m1b, m2W, m2b);

    for (int l = 0; l < Lc; l++) {
        k_topk<<<Bc, 1024, Nc * sizeof(unsigned)>>>();
        k_select<<<(BNc + 255) / 256, 256>>>();
        k_qfill<<<(DMAXc + 7) / 8, 128>>>(preW + l * 2 * Dc * Dc + Dc * Dc);
        k_conv<<<(UMAXc + 7) / 8, 128>>>(preW + l * 2 * Dc * Dc, preb + l * Dc,
                                         postW + l * 12 * Dc * Dc, postb + l * Dc,
                                         outW + l * Dc * Dc, outb + l * Dc);
        k_fillscore<<<(BNc + 255) / 256, 256>>>();
        k_score<<<(DMAXc + 7) / 8, 128>>>(linW, m1W, m1b, m2W, m2b);
    }
    k_readout<<<1, 32>>>(out);
}